// round 1
// baseline (speedup 1.0000x reference)
#include <cuda_runtime.h>
#include <cuda_bf16.h>

#define NN 50000
#define HID 128
#define INDIM 64

// Scratch (allocation-free rule: __device__ globals)
__device__ float g_h[NN * HID];
__device__ float g_agg[NN * HID];
__device__ float g_nsrc[NN];   // degree counter -> norm_src
__device__ float g_ndst[NN];   // degree counter -> norm_dst

// ---------------- zero kernels ----------------
__global__ void zero_degs_kernel(float* a, float* b, int n) {
    int i = blockIdx.x * blockDim.x + threadIdx.x;
    if (i < n) { a[i] = 0.0f; b[i] = 0.0f; }
}

__global__ void zero_agg_kernel(float4* agg4, int n4) {
    int i = blockIdx.x * blockDim.x + threadIdx.x;
    if (i < n4) agg4[i] = make_float4(0.f, 0.f, 0.f, 0.f);
}

// ---------------- degree count ----------------
__global__ void degree_kernel(const int* __restrict__ src, const int* __restrict__ dst,
                              float* dsrc, float* ddst, int E) {
    int e = blockIdx.x * blockDim.x + threadIdx.x;
    if (e < E) {
        atomicAdd(&dsrc[src[e]], 1.0f);
        atomicAdd(&ddst[dst[e]], 1.0f);
    }
}

__global__ void norm_kernel(float* dsrc, float* ddst, int n) {
    int i = blockIdx.x * blockDim.x + threadIdx.x;
    if (i < n) {
        dsrc[i] = rsqrtf(fmaxf(dsrc[i], 1.0f));
        ddst[i] = rsqrtf(fmaxf(ddst[i], 1.0f));
    }
}

// ---------------- scatter (SpMM): agg[dst] += h[src] * norm_src[src] ----------------
// One warp per edge, float4 per lane (32 lanes * 16B = 512B = full 128-float row).
__global__ void scatter_kernel(const int* __restrict__ src, const int* __restrict__ dst,
                               const float* __restrict__ norm_src,
                               const float4* __restrict__ h4,
                               float4* __restrict__ agg4, int E) {
    int warp = (blockIdx.x * blockDim.x + threadIdx.x) >> 5;
    int lane = threadIdx.x & 31;
    if (warp >= E) return;
    int s = __ldg(&src[warp]);
    int d = __ldg(&dst[warp]);
    float ns = __ldg(&norm_src[s]);
    float4 v = h4[(long)s * 32 + lane];
    v.x *= ns; v.y *= ns; v.z *= ns; v.w *= ns;
    float4* p = agg4 + (long)d * 32 + lane;
    asm volatile("red.global.add.v4.f32 [%0], {%1, %2, %3, %4};"
                 :: "l"(p), "f"(v.x), "f"(v.y), "f"(v.z), "f"(v.w) : "memory");
}

// ---------------- GEMM + bias + relu (+ optional per-row scale) ----------------
// out[r, :] = relu(scale[r] * (X[r, :K] @ W[K,128]) + B[:])
// Block: 256 threads, 32 rows x 128 cols. Thread tile: 4 rows x 4 cols.
template <int K>
__global__ void gemm_relu_kernel(const float* __restrict__ X, const float* __restrict__ W,
                                 const float* __restrict__ B,
                                 const float* __restrict__ rowscale,
                                 float* __restrict__ out, int n) {
    extern __shared__ float sm[];
    float* w_sh = sm;             // K * 128
    float* x_sh = sm + K * 128;   // 32 * K

    const int tx = threadIdx.x;
    const int row0 = blockIdx.x * 32;

    // Load W (K*128 floats) as float4
    {
        const float4* W4 = (const float4*)W;
        float4* w4 = (float4*)w_sh;
        #pragma unroll
        for (int i = tx; i < K * 32; i += 256) w4[i] = W4[i];
    }
    // Load X tile (32 rows x K), clamp row for tail block
    {
        const float4* X4 = (const float4*)X;
        float4* x4 = (float4*)x_sh;
        constexpr int K4 = K / 4;
        for (int i = tx; i < 32 * K4; i += 256) {
            int r = i / K4;
            int c = i - r * K4;
            int gr = row0 + r;
            if (gr >= n) gr = n - 1;
            x4[r * K4 + c] = X4[(long)gr * K4 + c];
        }
    }
    __syncthreads();

    const int cg = tx & 31;   // column group -> cols [cg*4, cg*4+4)
    const int ng = tx >> 5;   // row group    -> rows [ng*4, ng*4+4)

    float acc[4][4];
    #pragma unroll
    for (int i = 0; i < 4; i++)
        #pragma unroll
        for (int j = 0; j < 4; j++) acc[i][j] = 0.0f;

    #pragma unroll 8
    for (int k = 0; k < K; k++) {
        float4 w = *(const float4*)&w_sh[k * 128 + cg * 4];
        #pragma unroll
        for (int i = 0; i < 4; i++) {
            float xv = x_sh[(ng * 4 + i) * K + k];  // warp-broadcast
            acc[i][0] = fmaf(xv, w.x, acc[i][0]);
            acc[i][1] = fmaf(xv, w.y, acc[i][1]);
            acc[i][2] = fmaf(xv, w.z, acc[i][2]);
            acc[i][3] = fmaf(xv, w.w, acc[i][3]);
        }
    }

    float4 bv = *(const float4*)&B[cg * 4];
    #pragma unroll
    for (int i = 0; i < 4; i++) {
        int r = row0 + ng * 4 + i;
        if (r < n) {
            float sc = rowscale ? __ldg(&rowscale[r]) : 1.0f;
            float4 o;
            o.x = fmaxf(fmaf(acc[i][0], sc, bv.x), 0.0f);
            o.y = fmaxf(fmaf(acc[i][1], sc, bv.y), 0.0f);
            o.z = fmaxf(fmaf(acc[i][2], sc, bv.z), 0.0f);
            o.w = fmaxf(fmaf(acc[i][3], sc, bv.w), 0.0f);
            *(float4*)&out[(long)r * 128 + cg * 4] = o;
        }
    }
}

extern "C" void kernel_launch(void* const* d_in, const int* in_sizes, int n_in,
                              void* d_out, int out_size) {
    const float* x_raw = (const float*)d_in[0];   // [N, 64]
    const int*   src   = (const int*)d_in[1];     // [E]
    const int*   dst   = (const int*)d_in[2];     // [E]
    const float* Wp    = (const float*)d_in[3];   // [64, 128]
    const float* bp    = (const float*)d_in[4];   // [128]
    const float* Wl    = (const float*)d_in[5];   // [3, 128, 128]
    const float* bl    = (const float*)d_in[6];   // [3, 128]
    float* out = (float*)d_out;                   // [N, 128]

    const int N = in_sizes[0] / INDIM;
    const int E = in_sizes[1];

    float *h, *agg, *nsrc, *ndst;
    cudaGetSymbolAddress((void**)&h, g_h);
    cudaGetSymbolAddress((void**)&agg, g_agg);
    cudaGetSymbolAddress((void**)&nsrc, g_nsrc);
    cudaGetSymbolAddress((void**)&ndst, g_ndst);

    // Allow >48KB dynamic shared for the K=128 GEMM (host-side, not captured)
    cudaFuncSetAttribute(gemm_relu_kernel<128>,
                         cudaFuncAttributeMaxDynamicSharedMemorySize,
                         (128 * 128 + 32 * 128) * (int)sizeof(float));
    cudaFuncSetAttribute(gemm_relu_kernel<64>,
                         cudaFuncAttributeMaxDynamicSharedMemorySize,
                         (64 * 128 + 32 * 64) * (int)sizeof(float));

    // 1) degrees -> norms
    zero_degs_kernel<<<(N + 255) / 256, 256>>>(nsrc, ndst, N);
    degree_kernel<<<(E + 255) / 256, 256>>>(src, dst, nsrc, ndst, E);
    norm_kernel<<<(N + 255) / 256, 256>>>(nsrc, ndst, N);

    // 2) input projection + relu: h = relu(x_raw @ Wp + bp)
    {
        int smem = (64 * 128 + 32 * 64) * (int)sizeof(float);
        gemm_relu_kernel<64><<<(N + 31) / 32, 256, smem>>>(x_raw, Wp, bp, nullptr, h, N);
    }

    // 3) layers
    const int n4 = N * HID / 4;
    const int scatter_blocks = (E * 32 + 255) / 256;
    for (int l = 0; l < 3; l++) {
        zero_agg_kernel<<<(n4 + 255) / 256, 256>>>((float4*)agg, n4);
        scatter_kernel<<<scatter_blocks, 256>>>(src, dst, nsrc, (const float4*)h,
                                                (float4*)agg, E);
        float* o = (l == 2) ? out : h;
        int smem = (128 * 128 + 32 * 128) * (int)sizeof(float);
        gemm_relu_kernel<128><<<(N + 31) / 32, 256, smem>>>(
            agg, Wl + (long)l * 128 * 128, bl + (long)l * 128, ndst, o, N);
    }
}

// round 2
// speedup vs baseline: 1.1240x; 1.1240x over previous
#include <cuda_runtime.h>
#include <cuda_bf16.h>

#define NN 50000
#define EE 800000
#define HID 128
#define INDIM 64

// Scratch (allocation-free rule: __device__ globals)
__device__ float g_h[NN * HID];
__device__ float g_agg[NN * HID];
__device__ float g_nsrc[NN];
__device__ float g_ndst[NN];
__device__ int   g_dego[NN];       // out-degree (src occurrences)
__device__ int   g_degi[NN];       // in-degree  (dst occurrences)
__device__ int   g_off[NN + 1];    // CSR row offsets (by dst)
__device__ int   g_cur[NN];        // fill cursors
__device__ int   g_csr[EE];        // src index per CSR slot

// ---------------- zero degree counters ----------------
__global__ void zero_deg_kernel(int* a, int* b, int n) {
    int i = blockIdx.x * blockDim.x + threadIdx.x;
    if (i < n) { a[i] = 0; b[i] = 0; }
}

// ---------------- degree count ----------------
__global__ void degree_kernel(const int* __restrict__ src, const int* __restrict__ dst,
                              int* dego, int* degi, int E) {
    int e = blockIdx.x * blockDim.x + threadIdx.x;
    if (e < E) {
        atomicAdd(&dego[src[e]], 1);
        atomicAdd(&degi[dst[e]], 1);
    }
}

// ---------------- single-block exclusive scan + norms ----------------
__global__ void scan_kernel(const int* __restrict__ degi, const int* __restrict__ dego,
                            int* off, int* cur, float* nsrc, float* ndst, int N) {
    __shared__ int ssum[1024];
    const int t = threadIdx.x;
    const int chunk = (N + 1023) >> 10;
    const int b = t * chunk;
    const int e = min(b + chunk, N);
    int s = 0;
    for (int i = b; i < e; i++) s += degi[i];
    ssum[t] = s;
    __syncthreads();
    // inclusive Hillis-Steele scan over 1024 partials
    for (int d = 1; d < 1024; d <<= 1) {
        int v = (t >= d) ? ssum[t - d] : 0;
        __syncthreads();
        ssum[t] += v;
        __syncthreads();
    }
    int run = (t > 0) ? ssum[t - 1] : 0;
    for (int i = b; i < e; i++) {
        off[i] = run;
        cur[i] = run;
        int di = degi[i];
        run += di;
        ndst[i] = rsqrtf((float)max(di, 1));
        nsrc[i] = rsqrtf((float)max(dego[i], 1));
    }
    if (t == 1023) off[N] = ssum[1023];
}

// ---------------- CSR fill (order within bucket arbitrary; fp-sum tolerance covers it) ----
__global__ void fill_kernel(const int* __restrict__ src, const int* __restrict__ dst,
                            int* cur, int* csr, int E) {
    int e = blockIdx.x * blockDim.x + threadIdx.x;
    if (e < E) {
        int p = atomicAdd(&cur[dst[e]], 1);
        csr[p] = src[e];
    }
}

// ---------------- pull SpMM: agg[d] = ndst[d] * sum_{s in in(d)} h[s] ----------------
// One warp per dst node; lane owns a float4 (4 of 128 cols).
__global__ void pull_kernel(const int* __restrict__ off, const int* __restrict__ csr,
                            const float* __restrict__ ndst,
                            const float4* __restrict__ h4, float4* __restrict__ agg4, int N) {
    int w = (blockIdx.x * blockDim.x + threadIdx.x) >> 5;
    int lane = threadIdx.x & 31;
    if (w >= N) return;
    int beg = __ldg(&off[w]);
    int end = __ldg(&off[w + 1]);
    float4 acc = make_float4(0.f, 0.f, 0.f, 0.f);
    for (int j0 = beg; j0 < end; j0 += 32) {
        int j = j0 + lane;
        int s = (j < end) ? __ldg(&csr[j]) : 0;
        int cnt = min(32, end - j0);
        for (int t = 0; t < cnt; t++) {
            int ss = __shfl_sync(0xffffffffu, s, t);
            float4 v = h4[(long)ss * 32 + lane];
            acc.x += v.x; acc.y += v.y; acc.z += v.z; acc.w += v.w;
        }
    }
    float nd = __ldg(&ndst[w]);
    acc.x *= nd; acc.y *= nd; acc.z *= nd; acc.w *= nd;
    agg4[(long)w * 32 + lane] = acc;
}

// ---------------- GEMM + bias + relu + optional per-row post-scale ----------------
// out[r,:] = relu(X[r,:K] @ W[K,128] + B) * (postscale ? postscale[r] : 1)
// Block: 256 threads, 64 rows x 128 cols. Thread tile: 8 rows x 4 cols, k-chunk 4.
template <int K>
__global__ void gemm_relu_kernel(const float* __restrict__ X, const float* __restrict__ W,
                                 const float* __restrict__ B,
                                 const float* __restrict__ postscale,
                                 float* __restrict__ out, int n) {
    extern __shared__ float sm[];
    float* w_sh = sm;              // K * 128
    float* x_sh = sm + K * 128;    // 64 * K

    const int tx = threadIdx.x;
    const int row0 = blockIdx.x * 64;
    constexpr int K4 = K / 4;

    // Load W (K x 128) as float4
    {
        const float4* W4 = (const float4*)W;
        float4* w4 = (float4*)w_sh;
        #pragma unroll
        for (int i = tx; i < K * 32; i += 256) w4[i] = W4[i];
    }
    // Load X tile (64 rows x K); clamp rows in the tail block
    {
        const float4* X4 = (const float4*)X;
        float4* x4 = (float4*)x_sh;
        #pragma unroll
        for (int i = tx; i < 64 * K4; i += 256) {
            int r = i / K4;
            int c = i - r * K4;
            int gr = row0 + r;
            if (gr >= n) gr = n - 1;
            x4[i] = X4[(long)gr * K4 + c];
        }
    }
    __syncthreads();

    const int cg = tx & 31;        // cols [cg*4, cg*4+4)
    const int rbase = (tx >> 5) * 8;

    float acc[8][4];
    #pragma unroll
    for (int i = 0; i < 8; i++)
        #pragma unroll
        for (int j = 0; j < 4; j++) acc[i][j] = 0.0f;

    #pragma unroll 2
    for (int k = 0; k < K; k += 4) {
        float4 wv[4];
        #pragma unroll
        for (int t = 0; t < 4; t++)
            wv[t] = *(const float4*)&w_sh[(k + t) * 128 + cg * 4];
        #pragma unroll
        for (int i = 0; i < 8; i++) {
            float4 xv = *(const float4*)&x_sh[(rbase + i) * K + k];
            acc[i][0] = fmaf(xv.x, wv[0].x, acc[i][0]);
            acc[i][1] = fmaf(xv.x, wv[0].y, acc[i][1]);
            acc[i][2] = fmaf(xv.x, wv[0].z, acc[i][2]);
            acc[i][3] = fmaf(xv.x, wv[0].w, acc[i][3]);
            acc[i][0] = fmaf(xv.y, wv[1].x, acc[i][0]);
            acc[i][1] = fmaf(xv.y, wv[1].y, acc[i][1]);
            acc[i][2] = fmaf(xv.y, wv[1].z, acc[i][2]);
            acc[i][3] = fmaf(xv.y, wv[1].w, acc[i][3]);
            acc[i][0] = fmaf(xv.z, wv[2].x, acc[i][0]);
            acc[i][1] = fmaf(xv.z, wv[2].y, acc[i][1]);
            acc[i][2] = fmaf(xv.z, wv[2].z, acc[i][2]);
            acc[i][3] = fmaf(xv.z, wv[2].w, acc[i][3]);
            acc[i][0] = fmaf(xv.w, wv[3].x, acc[i][0]);
            acc[i][1] = fmaf(xv.w, wv[3].y, acc[i][1]);
            acc[i][2] = fmaf(xv.w, wv[3].z, acc[i][2]);
            acc[i][3] = fmaf(xv.w, wv[3].w, acc[i][3]);
        }
    }

    float4 bv = ((const float4*)B)[cg];
    #pragma unroll
    for (int i = 0; i < 8; i++) {
        int r = row0 + rbase + i;
        if (r < n) {
            float sc = postscale ? __ldg(&postscale[r]) : 1.0f;
            float4 o;
            o.x = fmaxf(acc[i][0] + bv.x, 0.0f) * sc;
            o.y = fmaxf(acc[i][1] + bv.y, 0.0f) * sc;
            o.z = fmaxf(acc[i][2] + bv.z, 0.0f) * sc;
            o.w = fmaxf(acc[i][3] + bv.w, 0.0f) * sc;
            *(float4*)&out[(long)r * 128 + cg * 4] = o;
        }
    }
}

extern "C" void kernel_launch(void* const* d_in, const int* in_sizes, int n_in,
                              void* d_out, int out_size) {
    const float* x_raw = (const float*)d_in[0];   // [N, 64]
    const int*   src   = (const int*)d_in[1];     // [E]
    const int*   dst   = (const int*)d_in[2];     // [E]
    const float* Wp    = (const float*)d_in[3];   // [64, 128]
    const float* bp    = (const float*)d_in[4];   // [128]
    const float* Wl    = (const float*)d_in[5];   // [3, 128, 128]
    const float* bl    = (const float*)d_in[6];   // [3, 128]
    float* out = (float*)d_out;                   // [N, 128]

    const int N = in_sizes[0] / INDIM;
    const int E = in_sizes[1];

    float *h, *agg, *nsrc, *ndst;
    int *dego, *degi, *off, *cur, *csr;
    cudaGetSymbolAddress((void**)&h, g_h);
    cudaGetSymbolAddress((void**)&agg, g_agg);
    cudaGetSymbolAddress((void**)&nsrc, g_nsrc);
    cudaGetSymbolAddress((void**)&ndst, g_ndst);
    cudaGetSymbolAddress((void**)&dego, g_dego);
    cudaGetSymbolAddress((void**)&degi, g_degi);
    cudaGetSymbolAddress((void**)&off, g_off);
    cudaGetSymbolAddress((void**)&cur, g_cur);
    cudaGetSymbolAddress((void**)&csr, g_csr);

    cudaFuncSetAttribute(gemm_relu_kernel<128>,
                         cudaFuncAttributeMaxDynamicSharedMemorySize,
                         (128 * 128 + 64 * 128) * (int)sizeof(float));
    cudaFuncSetAttribute(gemm_relu_kernel<64>,
                         cudaFuncAttributeMaxDynamicSharedMemorySize,
                         (64 * 128 + 64 * 64) * (int)sizeof(float));

    // 1) degrees -> norms + CSR(by dst)
    zero_deg_kernel<<<(N + 255) / 256, 256>>>(dego, degi, N);
    degree_kernel<<<(E + 255) / 256, 256>>>(src, dst, dego, degi, E);
    scan_kernel<<<1, 1024>>>(degi, dego, off, cur, nsrc, ndst, N);
    fill_kernel<<<(E + 255) / 256, 256>>>(src, dst, cur, csr, E);

    // 2) h = relu(x_raw @ Wp + bp) * norm_src   (norm_src pre-folded for layer-0 SpMM)
    {
        int smem = (64 * 128 + 64 * 64) * (int)sizeof(float);
        gemm_relu_kernel<64><<<(N + 63) / 64, 256, smem>>>(x_raw, Wp, bp, nsrc, h, N);
    }

    // 3) layers: pull-SpMM (folds norm_dst) then GEMM (folds next norm_src)
    const int pull_blocks = (N * 32 + 255) / 256;
    const int smem128 = (128 * 128 + 64 * 128) * (int)sizeof(float);
    for (int l = 0; l < 3; l++) {
        pull_kernel<<<pull_blocks, 256>>>(off, csr, ndst, (const float4*)h, (float4*)agg, N);
        float* o = (l == 2) ? out : h;
        const float* ps = (l == 2) ? nullptr : nsrc;
        gemm_relu_kernel<128><<<(N + 63) / 64, 256, smem128>>>(
            agg, Wl + (long)l * 128 * 128, bl + (long)l * 128, ps, o, N);
    }
}

// round 3
// speedup vs baseline: 1.6899x; 1.5034x over previous
#include <cuda_runtime.h>
#include <cuda_bf16.h>

#define NN 50000
#define EE 800000
#define HID 128
#define INDIM 64
#define SCAN_T 2048

// Scratch (allocation-free rule: __device__ globals)
__device__ float g_h[NN * HID];
__device__ float g_agg[NN * HID];
__device__ float g_nsrc[NN];
__device__ float g_ndst[NN];
__device__ int   g_dego[NN];
__device__ int   g_degi[NN];
__device__ int   g_off[NN + 1];
__device__ int   g_cur[NN];
__device__ int   g_csr[EE];
__device__ int   g_tsum[SCAN_T];

// ---------------- f32x2 packed helpers (Blackwell) ----------------
__device__ __forceinline__ unsigned long long pack2(float a, float b) {
    unsigned long long r;
    asm("mov.b64 %0, {%1, %2};" : "=l"(r) : "f"(a), "f"(b));
    return r;
}
__device__ __forceinline__ void unpack2(unsigned long long v, float& a, float& b) {
    asm("mov.b64 {%0, %1}, %2;" : "=f"(a), "=f"(b) : "l"(v));
}
__device__ __forceinline__ void addx2(unsigned long long& acc, unsigned long long v) {
    asm("add.rn.f32x2 %0, %0, %1;" : "+l"(acc) : "l"(v));
}
__device__ __forceinline__ void mulx2(unsigned long long& acc, unsigned long long v) {
    asm("mul.rn.f32x2 %0, %0, %1;" : "+l"(acc) : "l"(v));
}

// ---------------- zero degree counters ----------------
__global__ void zero_deg_kernel(int* a, int* b, int n) {
    int i = blockIdx.x * blockDim.x + threadIdx.x;
    if (i < n) { a[i] = 0; b[i] = 0; }
}

// ---------------- degree count ----------------
__global__ void degree_kernel(const int* __restrict__ src, const int* __restrict__ dst,
                              int* dego, int* degi, int E) {
    int e = blockIdx.x * blockDim.x + threadIdx.x;
    if (e < E) {
        atomicAdd(&dego[src[e]], 1);
        atomicAdd(&degi[dst[e]], 1);
    }
}

// ---------------- scan phase A: per-chunk partial sums ----------------
__global__ void partsum_kernel(const int* __restrict__ degi, int* tsum, int N) {
    int t = blockIdx.x * blockDim.x + threadIdx.x;
    if (t >= SCAN_T) return;
    int chunk = (N + SCAN_T - 1) / SCAN_T;
    int b = t * chunk, e = min(b + chunk, N);
    int s = 0;
    for (int i = b; i < e; i++) s += degi[i];
    tsum[t] = s;
}

// ---------------- scan phase B: exclusive scan of 2048 partials, 1 block ----------------
__global__ void scanpart_kernel(int* tsum) {
    __shared__ int sm[1024];
    int t = threadIdx.x;
    int a = tsum[2 * t], b = tsum[2 * t + 1];
    sm[t] = a + b;
    __syncthreads();
    for (int d = 1; d < 1024; d <<= 1) {
        int v = (t >= d) ? sm[t - d] : 0;
        __syncthreads();
        sm[t] += v;
        __syncthreads();
    }
    int excl = (t > 0) ? sm[t - 1] : 0;
    tsum[2 * t] = excl;
    tsum[2 * t + 1] = excl + a;
}

// ---------------- scan phase C: write offsets, cursors, norms ----------------
__global__ void writeoff_kernel(const int* __restrict__ degi, const int* __restrict__ dego,
                                const int* __restrict__ tsum,
                                int* off, int* cur, float* nsrc, float* ndst, int N) {
    int t = blockIdx.x * blockDim.x + threadIdx.x;
    if (t >= SCAN_T) return;
    int chunk = (N + SCAN_T - 1) / SCAN_T;
    int b = t * chunk, e = min(b + chunk, N);
    int run = tsum[t];
    for (int i = b; i < e; i++) {
        off[i] = run;
        cur[i] = run;
        int di = degi[i];
        run += di;
        ndst[i] = rsqrtf((float)max(di, 1));
        nsrc[i] = rsqrtf((float)max(dego[i], 1));
    }
    if (t == SCAN_T - 1) off[N] = run;
}

// ---------------- CSR fill ----------------
__global__ void fill_kernel(const int* __restrict__ src, const int* __restrict__ dst,
                            int* cur, int* csr, int E) {
    int e = blockIdx.x * blockDim.x + threadIdx.x;
    if (e < E) {
        int p = atomicAdd(&cur[dst[e]], 1);
        csr[p] = src[e];
    }
}

// ---------------- pull SpMM: agg[d] = ndst[d] * sum_{s in in(d)} h[s] ----------------
// One warp per dst node; lane owns a float4. 4-edge unrolled, f32x2 adds.
__global__ void pull_kernel(const int* __restrict__ off, const int* __restrict__ csr,
                            const float* __restrict__ ndst,
                            const float4* __restrict__ h4, float4* __restrict__ agg4, int N) {
    int w = (blockIdx.x * blockDim.x + threadIdx.x) >> 5;
    int lane = threadIdx.x & 31;
    if (w >= N) return;
    int beg = __ldg(&off[w]);
    int end = __ldg(&off[w + 1]);

    unsigned long long a0 = 0, a1 = 0;  // bit pattern of {0.f,0.f}
    a0 = pack2(0.f, 0.f); a1 = a0;

    int j = beg;
    for (; j + 4 <= end; j += 4) {
        int s0 = __ldg(&csr[j]);
        int s1 = __ldg(&csr[j + 1]);
        int s2 = __ldg(&csr[j + 2]);
        int s3 = __ldg(&csr[j + 3]);
        float4 v0 = __ldg(&h4[(long)s0 * 32 + lane]);
        float4 v1 = __ldg(&h4[(long)s1 * 32 + lane]);
        float4 v2 = __ldg(&h4[(long)s2 * 32 + lane]);
        float4 v3 = __ldg(&h4[(long)s3 * 32 + lane]);
        addx2(a0, pack2(v0.x, v0.y)); addx2(a1, pack2(v0.z, v0.w));
        addx2(a0, pack2(v1.x, v1.y)); addx2(a1, pack2(v1.z, v1.w));
        addx2(a0, pack2(v2.x, v2.y)); addx2(a1, pack2(v2.z, v2.w));
        addx2(a0, pack2(v3.x, v3.y)); addx2(a1, pack2(v3.z, v3.w));
    }
    for (; j < end; j++) {
        int s = __ldg(&csr[j]);
        float4 v = __ldg(&h4[(long)s * 32 + lane]);
        addx2(a0, pack2(v.x, v.y));
        addx2(a1, pack2(v.z, v.w));
    }

    float nd = __ldg(&ndst[w]);
    unsigned long long nn = pack2(nd, nd);
    mulx2(a0, nn);
    mulx2(a1, nn);
    float4 o;
    unpack2(a0, o.x, o.y);
    unpack2(a1, o.z, o.w);
    agg4[(long)w * 32 + lane] = o;
}

// ---------------- GEMM + bias + relu + optional per-row post-scale ----------------
template <int K>
__global__ void gemm_relu_kernel(const float* __restrict__ X, const float* __restrict__ W,
                                 const float* __restrict__ B,
                                 const float* __restrict__ postscale,
                                 float* __restrict__ out, int n) {
    extern __shared__ float sm[];
    float* w_sh = sm;              // K * 128
    float* x_sh = sm + K * 128;    // 64 * K

    const int tx = threadIdx.x;
    const int row0 = blockIdx.x * 64;
    constexpr int K4 = K / 4;

    {
        const float4* W4 = (const float4*)W;
        float4* w4 = (float4*)w_sh;
        #pragma unroll
        for (int i = tx; i < K * 32; i += 256) w4[i] = W4[i];
    }
    {
        const float4* X4 = (const float4*)X;
        float4* x4 = (float4*)x_sh;
        #pragma unroll
        for (int i = tx; i < 64 * K4; i += 256) {
            int r = i / K4;
            int c = i - r * K4;
            int gr = row0 + r;
            if (gr >= n) gr = n - 1;
            x4[i] = X4[(long)gr * K4 + c];
        }
    }
    __syncthreads();

    const int cg = tx & 31;
    const int rbase = (tx >> 5) * 8;

    float acc[8][4];
    #pragma unroll
    for (int i = 0; i < 8; i++)
        #pragma unroll
        for (int j = 0; j < 4; j++) acc[i][j] = 0.0f;

    #pragma unroll 2
    for (int k = 0; k < K; k += 4) {
        float4 wv[4];
        #pragma unroll
        for (int t = 0; t < 4; t++)
            wv[t] = *(const float4*)&w_sh[(k + t) * 128 + cg * 4];
        #pragma unroll
        for (int i = 0; i < 8; i++) {
            float4 xv = *(const float4*)&x_sh[(rbase + i) * K + k];
            acc[i][0] = fmaf(xv.x, wv[0].x, acc[i][0]);
            acc[i][1] = fmaf(xv.x, wv[0].y, acc[i][1]);
            acc[i][2] = fmaf(xv.x, wv[0].z, acc[i][2]);
            acc[i][3] = fmaf(xv.x, wv[0].w, acc[i][3]);
            acc[i][0] = fmaf(xv.y, wv[1].x, acc[i][0]);
            acc[i][1] = fmaf(xv.y, wv[1].y, acc[i][1]);
            acc[i][2] = fmaf(xv.y, wv[1].z, acc[i][2]);
            acc[i][3] = fmaf(xv.y, wv[1].w, acc[i][3]);
            acc[i][0] = fmaf(xv.z, wv[2].x, acc[i][0]);
            acc[i][1] = fmaf(xv.z, wv[2].y, acc[i][1]);
            acc[i][2] = fmaf(xv.z, wv[2].z, acc[i][2]);
            acc[i][3] = fmaf(xv.z, wv[2].w, acc[i][3]);
            acc[i][0] = fmaf(xv.w, wv[3].x, acc[i][0]);
            acc[i][1] = fmaf(xv.w, wv[3].y, acc[i][1]);
            acc[i][2] = fmaf(xv.w, wv[3].z, acc[i][2]);
            acc[i][3] = fmaf(xv.w, wv[3].w, acc[i][3]);
        }
    }

    float4 bv = ((const float4*)B)[cg];
    #pragma unroll
    for (int i = 0; i < 8; i++) {
        int r = row0 + rbase + i;
        if (r < n) {
            float sc = postscale ? __ldg(&postscale[r]) : 1.0f;
            float4 o;
            o.x = fmaxf(acc[i][0] + bv.x, 0.0f) * sc;
            o.y = fmaxf(acc[i][1] + bv.y, 0.0f) * sc;
            o.z = fmaxf(acc[i][2] + bv.z, 0.0f) * sc;
            o.w = fmaxf(acc[i][3] + bv.w, 0.0f) * sc;
            *(float4*)&out[(long)r * 128 + cg * 4] = o;
        }
    }
}

extern "C" void kernel_launch(void* const* d_in, const int* in_sizes, int n_in,
                              void* d_out, int out_size) {
    const float* x_raw = (const float*)d_in[0];
    const int*   src   = (const int*)d_in[1];
    const int*   dst   = (const int*)d_in[2];
    const float* Wp    = (const float*)d_in[3];
    const float* bp    = (const float*)d_in[4];
    const float* Wl    = (const float*)d_in[5];
    const float* bl    = (const float*)d_in[6];
    float* out = (float*)d_out;

    const int N = in_sizes[0] / INDIM;
    const int E = in_sizes[1];

    float *h, *agg, *nsrc, *ndst;
    int *dego, *degi, *off, *cur, *csr, *tsum;
    cudaGetSymbolAddress((void**)&h, g_h);
    cudaGetSymbolAddress((void**)&agg, g_agg);
    cudaGetSymbolAddress((void**)&nsrc, g_nsrc);
    cudaGetSymbolAddress((void**)&ndst, g_ndst);
    cudaGetSymbolAddress((void**)&dego, g_dego);
    cudaGetSymbolAddress((void**)&degi, g_degi);
    cudaGetSymbolAddress((void**)&off, g_off);
    cudaGetSymbolAddress((void**)&cur, g_cur);
    cudaGetSymbolAddress((void**)&csr, g_csr);
    cudaGetSymbolAddress((void**)&tsum, g_tsum);

    cudaFuncSetAttribute(gemm_relu_kernel<128>,
                         cudaFuncAttributeMaxDynamicSharedMemorySize,
                         (128 * 128 + 64 * 128) * (int)sizeof(float));
    cudaFuncSetAttribute(gemm_relu_kernel<64>,
                         cudaFuncAttributeMaxDynamicSharedMemorySize,
                         (64 * 128 + 64 * 64) * (int)sizeof(float));

    // 1) degrees -> norms + CSR(by dst), parallel scan
    zero_deg_kernel<<<(N + 255) / 256, 256>>>(dego, degi, N);
    degree_kernel<<<(E + 255) / 256, 256>>>(src, dst, dego, degi, E);
    partsum_kernel<<<SCAN_T / 256, 256>>>(degi, tsum, N);
    scanpart_kernel<<<1, 1024>>>(tsum);
    writeoff_kernel<<<SCAN_T / 256, 256>>>(degi, dego, tsum, off, cur, nsrc, ndst, N);
    fill_kernel<<<(E + 255) / 256, 256>>>(src, dst, cur, csr, E);

    // 2) h = relu(x_raw @ Wp + bp) * norm_src
    {
        int smem = (64 * 128 + 64 * 64) * (int)sizeof(float);
        gemm_relu_kernel<64><<<(N + 63) / 64, 256, smem>>>(x_raw, Wp, bp, nsrc, h, N);
    }

    // 3) layers: pull-SpMM (folds norm_dst) then GEMM (folds next norm_src)
    const int pull_blocks = (N * 32 + 255) / 256;
    const int smem128 = (128 * 128 + 64 * 128) * (int)sizeof(float);
    for (int l = 0; l < 3; l++) {
        pull_kernel<<<pull_blocks, 256>>>(off, csr, ndst, (const float4*)h, (float4*)agg, N);
        float* o = (l == 2) ? out : h;
        const float* ps = (l == 2) ? nullptr : nsrc;
        gemm_relu_kernel<128><<<(N + 63) / 64, 256, smem128>>>(
            agg, Wl + (long)l * 128 * 128, bl + (long)l * 128, ps, o, N);
    }
}

// round 5
// speedup vs baseline: 1.7784x; 1.0524x over previous
#include <cuda_runtime.h>
#include <cuda_fp16.h>
#include <cstdint>

#define NN 50000
#define EE 800000
#define SCAN_T 2048

// ---------------- scratch (__device__ globals; allocation-free) ----------------
__device__ __half g_h[NN * 128];       // activations in fp16 (gather-side)
__device__ float  g_agg[NN * 128];     // SpMM result fp32 (GEMM input)
__device__ float  g_nsrc[NN];
__device__ float  g_ndst[NN];
__device__ int    g_dego[NN];
__device__ int    g_degi[NN];
__device__ int    g_off[NN + 1];
__device__ int    g_cur[NN];
__device__ int    g_csr[EE];
__device__ int    g_tsum[SCAN_T];

// ---------------- f32x2 packed helpers (Blackwell) ----------------
__device__ __forceinline__ unsigned long long pack2(float a, float b) {
    unsigned long long r;
    asm("mov.b64 %0, {%1, %2};" : "=l"(r) : "f"(a), "f"(b));
    return r;
}
__device__ __forceinline__ void unpack2(unsigned long long v, float& a, float& b) {
    asm("mov.b64 {%0, %1}, %2;" : "=f"(a), "=f"(b) : "l"(v));
}
__device__ __forceinline__ void addx2(unsigned long long& acc, unsigned long long v) {
    asm("add.rn.f32x2 %0, %0, %1;" : "+l"(acc) : "l"(v));
}
__device__ __forceinline__ void mulx2(unsigned long long& acc, unsigned long long v) {
    asm("mul.rn.f32x2 %0, %0, %1;" : "+l"(acc) : "l"(v));
}

// ---------------- CSR build ----------------
__global__ void zero_deg_kernel(int* a, int* b, int n) {
    int i = blockIdx.x * blockDim.x + threadIdx.x;
    if (i < n) { a[i] = 0; b[i] = 0; }
}

// 4 edges per thread (int4 loads) for MLP; tail handled by thread 0.
__global__ void degree_kernel(const int* __restrict__ src, const int* __restrict__ dst,
                              int* dego, int* degi, int E) {
    int i = blockIdx.x * blockDim.x + threadIdx.x;
    int E4 = E >> 2;
    if (i < E4) {
        int4 s = __ldg((const int4*)src + i);
        int4 d = __ldg((const int4*)dst + i);
        atomicAdd(&dego[s.x], 1);
        atomicAdd(&dego[s.y], 1);
        atomicAdd(&dego[s.z], 1);
        atomicAdd(&dego[s.w], 1);
        atomicAdd(&degi[d.x], 1);
        atomicAdd(&degi[d.y], 1);
        atomicAdd(&degi[d.z], 1);
        atomicAdd(&degi[d.w], 1);
    }
    if (i == 0) {
        for (int e = E4 << 2; e < E; e++) {
            atomicAdd(&dego[src[e]], 1);
            atomicAdd(&degi[dst[e]], 1);
        }
    }
}

__global__ void partsum_kernel(const int* __restrict__ degi, int* tsum, int N) {
    int t = blockIdx.x * blockDim.x + threadIdx.x;
    if (t >= SCAN_T) return;
    int chunk = (N + SCAN_T - 1) / SCAN_T;
    int b = t * chunk, e = min(b + chunk, N);
    int s = 0;
    for (int i = b; i < e; i++) s += degi[i];
    tsum[t] = s;
}

__global__ void scanpart_kernel(int* tsum) {
    __shared__ int sm[1024];
    int t = threadIdx.x;
    int a = tsum[2 * t], b = tsum[2 * t + 1];
    sm[t] = a + b;
    __syncthreads();
    for (int d = 1; d < 1024; d <<= 1) {
        int v = (t >= d) ? sm[t - d] : 0;
        __syncthreads();
        sm[t] += v;
        __syncthreads();
    }
    int excl = (t > 0) ? sm[t - 1] : 0;
    tsum[2 * t] = excl;
    tsum[2 * t + 1] = excl + a;
}

__global__ void writeoff_kernel(const int* __restrict__ degi, const int* __restrict__ dego,
                                const int* __restrict__ tsum,
                                int* off, int* cur, float* nsrc, float* ndst, int N) {
    int t = blockIdx.x * blockDim.x + threadIdx.x;
    if (t >= SCAN_T) return;
    int chunk = (N + SCAN_T - 1) / SCAN_T;
    int b = t * chunk, e = min(b + chunk, N);
    int run = tsum[t];
    for (int i = b; i < e; i++) {
        off[i] = run;
        cur[i] = run;
        int di = degi[i];
        run += di;
        ndst[i] = rsqrtf((float)max(di, 1));
        nsrc[i] = rsqrtf((float)max(dego[i], 1));
    }
    if (t == SCAN_T - 1) off[N] = run;
}

// 4 edges per thread for MLP; tail by thread 0.
__global__ void fill_kernel(const int* __restrict__ src, const int* __restrict__ dst,
                            int* cur, int* csr, int E) {
    int i = blockIdx.x * blockDim.x + threadIdx.x;
    int E4 = E >> 2;
    if (i < E4) {
        int4 s = __ldg((const int4*)src + i);
        int4 d = __ldg((const int4*)dst + i);
        int p0 = atomicAdd(&cur[d.x], 1);
        int p1 = atomicAdd(&cur[d.y], 1);
        int p2 = atomicAdd(&cur[d.z], 1);
        int p3 = atomicAdd(&cur[d.w], 1);
        csr[p0] = s.x;
        csr[p1] = s.y;
        csr[p2] = s.z;
        csr[p3] = s.w;
    }
    if (i == 0) {
        for (int e = E4 << 2; e < E; e++) {
            int p = atomicAdd(&cur[dst[e]], 1);
            csr[p] = src[e];
        }
    }
}

// ---------------- pull SpMM: agg[d] = ndst[d] * sum_{s in in(d)} h[s] ----------------
// h is fp16: one row = 128 halves = 256B = 32 lanes x uint2 (4 cols/lane).
// One warp per dst node; 4-edge unrolled; fp32 accumulation with f32x2 adds.
__global__ void pull_kernel(const int* __restrict__ off, const int* __restrict__ csr,
                            const float* __restrict__ ndst,
                            const uint2* __restrict__ h2, float4* __restrict__ agg4, int N) {
    int w = (blockIdx.x * blockDim.x + threadIdx.x) >> 5;
    int lane = threadIdx.x & 31;
    if (w >= N) return;
    int beg = __ldg(&off[w]);
    int end = __ldg(&off[w + 1]);

    unsigned long long a0 = pack2(0.f, 0.f), a1 = a0;

    int j = beg;
    for (; j + 4 <= end; j += 4) {
        int s0 = __ldg(&csr[j]);
        int s1 = __ldg(&csr[j + 1]);
        int s2 = __ldg(&csr[j + 2]);
        int s3 = __ldg(&csr[j + 3]);
        uint2 v0 = __ldg(&h2[(long)s0 * 32 + lane]);
        uint2 v1 = __ldg(&h2[(long)s1 * 32 + lane]);
        uint2 v2 = __ldg(&h2[(long)s2 * 32 + lane]);
        uint2 v3 = __ldg(&h2[(long)s3 * 32 + lane]);
        float2 f;
        f = __half22float2(*(const __half2*)&v0.x); addx2(a0, pack2(f.x, f.y));
        f = __half22float2(*(const __half2*)&v0.y); addx2(a1, pack2(f.x, f.y));
        f = __half22float2(*(const __half2*)&v1.x); addx2(a0, pack2(f.x, f.y));
        f = __half22float2(*(const __half2*)&v1.y); addx2(a1, pack2(f.x, f.y));
        f = __half22float2(*(const __half2*)&v2.x); addx2(a0, pack2(f.x, f.y));
        f = __half22float2(*(const __half2*)&v2.y); addx2(a1, pack2(f.x, f.y));
        f = __half22float2(*(const __half2*)&v3.x); addx2(a0, pack2(f.x, f.y));
        f = __half22float2(*(const __half2*)&v3.y); addx2(a1, pack2(f.x, f.y));
    }
    for (; j < end; j++) {
        int s = __ldg(&csr[j]);
        uint2 v = __ldg(&h2[(long)s * 32 + lane]);
        float2 f;
        f = __half22float2(*(const __half2*)&v.x); addx2(a0, pack2(f.x, f.y));
        f = __half22float2(*(const __half2*)&v.y); addx2(a1, pack2(f.x, f.y));
    }

    float nd = __ldg(&ndst[w]);
    unsigned long long nn = pack2(nd, nd);
    mulx2(a0, nn);
    mulx2(a1, nn);
    float4 o;
    unpack2(a0, o.x, o.y);
    unpack2(a1, o.z, o.w);
    agg4[(long)w * 32 + lane] = o;
}

// ---------------- GEMM + bias + relu + optional per-row post-scale ----------------
// HALF_OUT=true: writes __half rows (for h, gather-side); else fp32 (final out).
// Block: 256 threads, 64 rows x 128 cols. Thread tile: 8 rows x 4 cols, k-chunk 4.
template <int K, bool HALF_OUT>
__global__ void gemm_relu_kernel(const float* __restrict__ X, const float* __restrict__ W,
                                 const float* __restrict__ B,
                                 const float* __restrict__ postscale,
                                 void* __restrict__ outv, int n) {
    extern __shared__ float sm[];
    float* w_sh = sm;              // K * 128
    float* x_sh = sm + K * 128;    // 64 * K

    const int tx = threadIdx.x;
    const int row0 = blockIdx.x * 64;
    constexpr int K4 = K / 4;

    {
        const float4* W4 = (const float4*)W;
        float4* w4 = (float4*)w_sh;
        #pragma unroll
        for (int i = tx; i < K * 32; i += 256) w4[i] = W4[i];
    }
    {
        const float4* X4 = (const float4*)X;
        float4* x4 = (float4*)x_sh;
        #pragma unroll
        for (int i = tx; i < 64 * K4; i += 256) {
            int r = i / K4;
            int c = i - r * K4;
            int gr = row0 + r;
            if (gr >= n) gr = n - 1;
            x4[i] = X4[(long)gr * K4 + c];
        }
    }
    __syncthreads();

    const int cg = tx & 31;
    const int rbase = (tx >> 5) * 8;

    float acc[8][4];
    #pragma unroll
    for (int i = 0; i < 8; i++)
        #pragma unroll
        for (int j = 0; j < 4; j++) acc[i][j] = 0.0f;

    #pragma unroll 2
    for (int k = 0; k < K; k += 4) {
        float4 wv[4];
        #pragma unroll
        for (int t = 0; t < 4; t++)
            wv[t] = *(const float4*)&w_sh[(k + t) * 128 + cg * 4];
        #pragma unroll
        for (int i = 0; i < 8; i++) {
            float4 xv = *(const float4*)&x_sh[(rbase + i) * K + k];
            acc[i][0] = fmaf(xv.x, wv[0].x, acc[i][0]);
            acc[i][1] = fmaf(xv.x, wv[0].y, acc[i][1]);
            acc[i][2] = fmaf(xv.x, wv[0].z, acc[i][2]);
            acc[i][3] = fmaf(xv.x, wv[0].w, acc[i][3]);
            acc[i][0] = fmaf(xv.y, wv[1].x, acc[i][0]);
            acc[i][1] = fmaf(xv.y, wv[1].y, acc[i][1]);
            acc[i][2] = fmaf(xv.y, wv[1].z, acc[i][2]);
            acc[i][3] = fmaf(xv.y, wv[1].w, acc[i][3]);
            acc[i][0] = fmaf(xv.z, wv[2].x, acc[i][0]);
            acc[i][1] = fmaf(xv.z, wv[2].y, acc[i][1]);
            acc[i][2] = fmaf(xv.z, wv[2].z, acc[i][2]);
            acc[i][3] = fmaf(xv.z, wv[2].w, acc[i][3]);
            acc[i][0] = fmaf(xv.w, wv[3].x, acc[i][0]);
            acc[i][1] = fmaf(xv.w, wv[3].y, acc[i][1]);
            acc[i][2] = fmaf(xv.w, wv[3].z, acc[i][2]);
            acc[i][3] = fmaf(xv.w, wv[3].w, acc[i][3]);
        }
    }

    float4 bv = ((const float4*)B)[cg];
    #pragma unroll
    for (int i = 0; i < 8; i++) {
        int r = row0 + rbase + i;
        if (r < n) {
            float sc = postscale ? __ldg(&postscale[r]) : 1.0f;
            float4 o;
            o.x = fmaxf(acc[i][0] + bv.x, 0.0f) * sc;
            o.y = fmaxf(acc[i][1] + bv.y, 0.0f) * sc;
            o.z = fmaxf(acc[i][2] + bv.z, 0.0f) * sc;
            o.w = fmaxf(acc[i][3] + bv.w, 0.0f) * sc;
            if (HALF_OUT) {
                __half2 p0 = __floats2half2_rn(o.x, o.y);
                __half2 p1 = __floats2half2_rn(o.z, o.w);
                uint2 st;
                st.x = *(uint32_t*)&p0;
                st.y = *(uint32_t*)&p1;
                *(uint2*)((__half*)outv + (long)r * 128 + cg * 4) = st;
            } else {
                *(float4*)((float*)outv + (long)r * 128 + cg * 4) = o;
            }
        }
    }
}

extern "C" void kernel_launch(void* const* d_in, const int* in_sizes, int n_in,
                              void* d_out, int out_size) {
    const float* x_raw = (const float*)d_in[0];
    const int*   src   = (const int*)d_in[1];
    const int*   dst   = (const int*)d_in[2];
    const float* Wp    = (const float*)d_in[3];
    const float* bp    = (const float*)d_in[4];
    const float* Wl    = (const float*)d_in[5];
    const float* bl    = (const float*)d_in[6];
    float* out = (float*)d_out;

    const int N = in_sizes[0] / 64;
    const int E = in_sizes[1];

    __half* h;
    float *agg, *nsrc, *ndst;
    int *dego, *degi, *off, *cur, *csr, *tsum;
    cudaGetSymbolAddress((void**)&h, g_h);
    cudaGetSymbolAddress((void**)&agg, g_agg);
    cudaGetSymbolAddress((void**)&nsrc, g_nsrc);
    cudaGetSymbolAddress((void**)&ndst, g_ndst);
    cudaGetSymbolAddress((void**)&dego, g_dego);
    cudaGetSymbolAddress((void**)&degi, g_degi);
    cudaGetSymbolAddress((void**)&off, g_off);
    cudaGetSymbolAddress((void**)&cur, g_cur);
    cudaGetSymbolAddress((void**)&csr, g_csr);
    cudaGetSymbolAddress((void**)&tsum, g_tsum);

    cudaFuncSetAttribute((const void*)gemm_relu_kernel<128, true>,
                         cudaFuncAttributeMaxDynamicSharedMemorySize,
                         (128 * 128 + 64 * 128) * (int)sizeof(float));
    cudaFuncSetAttribute((const void*)gemm_relu_kernel<128, false>,
                         cudaFuncAttributeMaxDynamicSharedMemorySize,
                         (128 * 128 + 64 * 128) * (int)sizeof(float));
    cudaFuncSetAttribute((const void*)gemm_relu_kernel<64, true>,
                         cudaFuncAttributeMaxDynamicSharedMemorySize,
                         (64 * 128 + 64 * 64) * (int)sizeof(float));

    // 1) degrees -> norms + CSR(by dst), parallel scan
    const int E4 = E >> 2;
    zero_deg_kernel<<<(N + 255) / 256, 256>>>(dego, degi, N);
    degree_kernel<<<(E4 + 255) / 256, 256>>>(src, dst, dego, degi, E);
    partsum_kernel<<<SCAN_T / 256, 256>>>(degi, tsum, N);
    scanpart_kernel<<<1, 1024>>>(tsum);
    writeoff_kernel<<<SCAN_T / 256, 256>>>(degi, dego, tsum, off, cur, nsrc, ndst, N);
    fill_kernel<<<(E4 + 255) / 256, 256>>>(src, dst, cur, csr, E);

    // 2) h = fp16( relu(x_raw @ Wp + bp) * norm_src )
    {
        int smem = (64 * 128 + 64 * 64) * (int)sizeof(float);
        gemm_relu_kernel<64, true><<<(N + 63) / 64, 256, smem>>>(x_raw, Wp, bp, nsrc, h, N);
    }

    // 3) layers: pull-SpMM (fp16 gather, folds norm_dst) then GEMM (folds next norm_src)
    const int pull_blocks = (N * 32 + 255) / 256;
    const int smem128 = (128 * 128 + 64 * 128) * (int)sizeof(float);
    for (int l = 0; l < 3; l++) {
        pull_kernel<<<pull_blocks, 256>>>(off, csr, ndst, (const uint2*)h, (float4*)agg, N);
        const float* Wcur = Wl + (long)l * 128 * 128;
        const float* bcur = bl + (long)l * 128;
        if (l == 2) {
            gemm_relu_kernel<128, false><<<(N + 63) / 64, 256, smem128>>>(
                agg, Wcur, bcur, nullptr, out, N);
        } else {
            gemm_relu_kernel<128, true><<<(N + 63) / 64, 256, smem128>>>(
                agg, Wcur, bcur, nsrc, h, N);
        }
    }
}